// round 16
// baseline (speedup 1.0000x reference)
#include <cuda_runtime.h>
#include <cuda_fp16.h>
#include <cstdint>
#include <cstddef>

#define BATCH   4
#define CIN     64
#define COUT    128
#define HH      64
#define WW      1024
#define HO      32
#define WO      512
#define NPIX    65536
#define KTOT    1024
#define OUT0    8388608
#define AZI_C   0.006135923151542565f
#define INC_C   0.0073f

__device__ __half g_m[(size_t)KTOT * NPIX];     // single fp16 plane
__device__ __half g_WcH[COUT * KTOT];           // fp16(Wc)
__device__ __half g_W2TH[CIN * CIN];            // fp16(W2^T) [c][j]
__device__ float  g_Ast[CIN * 16];              // [j][pos]

__device__ __forceinline__ uint32_t smem_u32(const void* p) {
    uint32_t a;
    asm("{ .reg .u64 t; cvta.to.shared.u64 t, %1; cvt.u32.u64 %0, t; }" : "=r"(a) : "l"(p));
    return a;
}
#define SWA(o) ((o) ^ (((o) >> 3) & 0x70))
#define SWC(o) ((o) ^ (((o) >> 5) & 0x70))

__device__ __forceinline__ void sts32(uint32_t saddr, uint32_t v) {
    asm volatile("st.shared.u32 [%0], %1;" :: "r"(saddr), "r"(v) : "memory");
}
__device__ __forceinline__ void sts16(uint32_t saddr, uint32_t v) {
    asm volatile("{ .reg .b16 h; cvt.u16.u32 h, %1; st.shared.b16 [%0], h; }"
        :: "r"(saddr), "r"(v) : "memory");
}
__device__ __forceinline__ float lds_h16(uint32_t saddr) {
    float v;
    asm volatile("{ .reg .b16 h; ld.shared.b16 h, [%1]; cvt.f32.f16 %0, h; }"
        : "=f"(v) : "r"(saddr));
    return v;
}
__device__ __forceinline__ void cp16(uint32_t saddr, const void* gaddr) {
    asm volatile("cp.async.cg.shared.global [%0], [%1], 16;" :: "r"(saddr), "l"(gaddr));
}
#define CP_COMMIT() asm volatile("cp.async.commit_group;" ::: "memory")
#define CP_WAIT2()  asm volatile("cp.async.wait_group 2;" ::: "memory")
#define CP_WAIT1()  asm volatile("cp.async.wait_group 1;" ::: "memory")
#define CP_WAIT0()  asm volatile("cp.async.wait_group 0;" ::: "memory")

__device__ __forceinline__ void ldsm4(uint32_t* r, uint32_t a) {
    asm volatile("ldmatrix.sync.aligned.m8n8.x4.shared.b16 {%0,%1,%2,%3}, [%4];"
        : "=r"(r[0]), "=r"(r[1]), "=r"(r[2]), "=r"(r[3]) : "r"(a));
}
__device__ __forceinline__ void ldsm4t(uint32_t* r, uint32_t a) {
    asm volatile("ldmatrix.sync.aligned.m8n8.x4.trans.shared.b16 {%0,%1,%2,%3}, [%4];"
        : "=r"(r[0]), "=r"(r[1]), "=r"(r[2]), "=r"(r[3]) : "r"(a));
}
__device__ __forceinline__ void mma16816(float* d, const uint32_t* a, const uint32_t* b) {
    asm volatile(
        "mma.sync.aligned.m16n8k16.row.col.f32.f16.f16.f32 "
        "{%0,%1,%2,%3}, {%4,%5,%6,%7}, {%8,%9}, {%0,%1,%2,%3};"
        : "+f"(d[0]), "+f"(d[1]), "+f"(d[2]), "+f"(d[3])
        : "r"(a[0]), "r"(a[1]), "r"(a[2]), "r"(a[3]), "r"(b[0]), "r"(b[1]));
}
__device__ __forceinline__ uint32_t pk_h2(float lo, float hi) {
    uint32_t r;
    asm("cvt.rn.f16x2.f32 %0, %1, %2;" : "=r"(r) : "f"(hi), "f"(lo));
    return r;
}

// =====================================================================
// Kernel 0: fp16(Wc), fp16(W2^T), Ast
// =====================================================================
__global__ void k0_prep(const float* __restrict__ Wc, const float* __restrict__ W2,
                        const float* __restrict__ W1) {
    int i = blockIdx.x * 256 + threadIdx.x;
    if (i < COUT * KTOT) {
        g_WcH[i] = __float2half_rn(Wc[i]);
    }
    if (i < CIN * CIN) {
        int j = i >> 6, c = i & 63;
        g_W2TH[c * 64 + j] = __float2half_rn(W2[i]);
    }
    if (i < CIN * 16) {
        int j = i >> 4, pos = i & 15;
        int u = pos >> 2, v = pos & 3;
        float du = (float)(u - 2), dv = (float)(v - 2);
        float ca = cosf(AZI_C * dv), sa = sinf(AZI_C * dv);
        float ci = cosf(INC_C * du), si = sinf(INC_C * du);
        g_Ast[i] = ca * ci * W1[j] + ca * si * W1[64 + j] + sa * W1[128 + j];
    }
}

// =====================================================================
// Kernel 1 v7: fp16 path + fp16 x staged in smem. 3 CTAs/SM.
// 16-px tile, 256 threads, grid (32, 32, 4).
// smem map (64800 B):
//   0     HS/WS fp16 [64][512B SWC] (32768, time-shared h -> w)
//   32768 XS fp16 [64][4][36] (18432)
//   51200 W2TH (8192)
//   59392 Ast (4096)
//   63488 W10 (256) | 63744 b1 (256) | 64000 b2 (256)
//   64256 rs [4][34] (544)
// =====================================================================
#define V7_HS    0
#define V7_XS    32768
#define V7_W2TH  51200
#define V7_AST   59392
#define V7_W10   63488
#define V7_B1    63744
#define V7_B2    64000
#define V7_RS    64256
#define SM1_BYTES 64800

__global__ void __launch_bounds__(256, 3)
k1_weights(const float* __restrict__ x, const float* __restrict__ r,
           const float* __restrict__ W1, const float* __restrict__ b1,
           const float* __restrict__ b2, float* __restrict__ rcout)
{
    extern __shared__ float sm[];
    float* Ast  = sm + V7_AST / 4;
    float* W10s = sm + V7_W10 / 4;
    float* b1s  = sm + V7_B1 / 4;
    float* b2s  = sm + V7_B2 / 4;
    float* rs   = sm + V7_RS / 4;
    char*  smc  = (char*)sm;
    const uint32_t sb = smem_u32(sm);

    const int tid  = threadIdx.x;
    const int lane = tid & 31;
    const int wid  = tid >> 5;
    const int ho   = blockIdx.y;
    const int bz   = blockIdx.z;
    const int wo0  = blockIdx.x * 16;

    if (tid < 64) { W10s[tid] = W1[tid]; b1s[tid] = b1[tid]; b2s[tid] = b2[tid]; }
    for (int i = tid; i < 1024; i += 256) Ast[i] = g_Ast[i];
    if (tid < 4 * 34) {
        int v = tid / 34, cc = tid % 34;
        int rowp = 2 * ho + v;
        int row  = (rowp == 0) ? (HH - 1) : ((rowp == HH + 1) ? 0 : rowp - 1);
        int colp = 2 * wo0 + cc;
        float val;
        if (colp == 0 || colp == WW + 1) val = 100.0f;
        else val = r[((size_t)bz * HH + row) * WW + (colp - 1)];
        rs[tid] = val;
    }
    for (int i = tid; i < 4096; i += 256) {
        int row = i >> 6, col = i & 63;
        uint32_t off = SWA(row * 128 + col * 2);
        *(__half*)(smc + V7_W2TH + off) = g_W2TH[i];
    }
    // ---- xs staging: fp16 [64][4][36], cc in 0..33, division-free ----
    {
        int xr[4];
        #pragma unroll
        for (int v = 0; v < 4; v++) {
            int rowp = 2 * ho + v;
            xr[v] = (rowp == 0) ? (HH - 1) : ((rowp == HH + 1) ? 0 : rowp - 1);
        }
        const int gbase = 2 * wo0 - 1;
        #pragma unroll 4
        for (int it = 0; it < 32; it++) {       // cc 0..31
            int flat = tid + it * 256;
            int cc = flat & 31;
            int rv = flat >> 5;                 // c*4 + v
            int c = rv >> 2, v = rv & 3;
            int g = gbase + cc;
            float val = 0.0f;
            if (g >= 0 && g < WW)
                val = x[(((size_t)(bz * CIN + c)) * HH + xr[v]) * WW + g];
            *(__half*)(smc + V7_XS + (c * 144 + v * 36 + cc) * 2) = __float2half_rn(val);
        }
        #pragma unroll
        for (int it = 0; it < 2; it++) {        // cc in {32, 33}
            int flat = tid + it * 256;
            int cc = 32 + (flat & 1);
            int rv = flat >> 1;
            int c = rv >> 2, v = rv & 3;
            int g = gbase + cc;
            float val = 0.0f;
            if (g >= 0 && g < WW)
                val = x[(((size_t)(bz * CIN + c)) * HH + xr[v]) * WW + g];
            *(__half*)(smc + V7_XS + (c * 144 + v * 36 + cc) * 2) = __float2half_rn(val);
        }
    }
    __syncthreads();

    const size_t nbase = (size_t)bz * 16384 + (size_t)ho * 512 + wo0;

    // ---- h compute -> fp16 plane in HS ----
    {
        int pos = tid >> 4;
        int u = pos >> 2, v = pos & 3;
        int px = tid & 15;
        float R   = rs[v * 34 + 2 * px + u];
        float nrc = -rs[2 * 34 + 2 * px + 2];
        const int wordb = (tid & ~1) * 2;
        const bool evenl = ((lane & 1) == 0);
        #pragma unroll 8
        for (int j = 0; j < 64; j++) {
            float t = fmaf(R, Ast[j * 16 + pos], fmaf(nrc, W10s[j], b1s[j]));
            t = (t > 0.0f) ? t : 0.2f * t;
            float t_o = __shfl_xor_sync(0xffffffffu, t, 1);
            if (evenl) {
                uint32_t word = pk_h2(t, t_o);
                sts32(sb + V7_HS + SWC(j * 512 + wordb), word);
            }
        }
    }
    __syncthreads();

    // ---- w-GEMM: 8 warps, M16(c) x N128(combo), K=64, 1 combo ----
    {
        const int wm = (wid & 3) * 16;
        const int wn = (wid >> 2) * 128;

        float acc[16][4];
        #pragma unroll
        for (int nt = 0; nt < 16; nt++)
            #pragma unroll
            for (int q = 0; q < 4; q++) acc[nt][q] = 0.0f;

        #pragma unroll
        for (int ks = 0; ks < 4; ks++) {
            uint32_t aH[4];
            int arow  = wm + (lane & 15);
            int acolb = ks * 32 + ((lane >> 4) << 4);
            ldsm4(aH, sb + V7_W2TH + SWA(arow * 128 + acolb));
            int browb = (ks * 16 + (lane & 15)) * 512;
            #pragma unroll
            for (int g = 0; g < 8; g++) {
                uint32_t off = SWC(browb + wn * 2 + g * 32 + ((lane >> 4) << 4));
                uint32_t bh[4];
                ldsm4t(bh, sb + V7_HS + off);
                mma16816(acc[2*g],   aH, bh);
                mma16816(acc[2*g+1], aH, bh + 2);
            }
        }
        __syncthreads();   // h fully consumed; region becomes w

        int r0 = wm + (lane >> 2);
        int r2 = r0 + 8;
        float b2a = b2s[r0], b2b = b2s[r2];
        #pragma unroll
        for (int nt = 0; nt < 16; nt++) {
            int col = wn + nt * 8 + (lane & 3) * 2;
            uint32_t w01 = pk_h2(acc[nt][0] + b2a, acc[nt][1] + b2a);
            uint32_t w23 = pk_h2(acc[nt][2] + b2b, acc[nt][3] + b2b);
            sts32(sb + V7_HS + SWC(r0 * 512 + col * 2), w01);
            sts32(sb + V7_HS + SWC(r2 * 512 + col * 2), w23);
        }
    }
    __syncthreads();

    // ---- phase B: m = w * x (all smem) -> g_m (fp16) ----
    {
        int pos = 2 * wid + (lane >> 4);
        int u = pos >> 2, v = pos & 3;
        int px = lane & 15;
        int comb = pos * 16 + px;
        const uint32_t xsb = sb + V7_XS + (v * 36 + 2 * px + u) * 2;

        __half* gm = g_m + (size_t)pos * NPIX + nbase + px;
        #pragma unroll 8
        for (int c = 0; c < 64; c++) {
            float wv = lds_h16(sb + V7_HS + SWC(c * 512 + comb * 2));
            float xv = lds_h16(xsb + c * 288);
            gm[(size_t)c * 16 * NPIX] = __float2half_rn(wv * xv);
        }
    }

    if (rcout != nullptr && tid < 16) {
        rcout[nbase + tid] = rs[2 * 34 + 2 * tid + 2];
    }
}

// =====================================================================
// Kernel 2 v5: fp16 1-combo GEMM, 3-stage cp.async pipeline.
// 512 threads, N-tile 256, stage 48KB x3: A 16K | B 32K.
// =====================================================================
#define K2_STAGE 49152
#define K2_SMEM  (3 * K2_STAGE)

__global__ void __launch_bounds__(512, 1)
k2_hmma(const float* __restrict__ bc, float* __restrict__ out)
{
    extern __shared__ char sm2[];
    const uint32_t sb = smem_u32(sm2);
    const int tid  = threadIdx.x;
    const int wid  = tid >> 5;
    const int lane = tid & 31;
    const int n0 = blockIdx.x * 256;
    const int wm = (wid & 3) * 32;
    const int wn = (wid >> 2) * 64;

    float acc[2][8][4];
    #pragma unroll
    for (int mi = 0; mi < 2; mi++)
        #pragma unroll
        for (int nt = 0; nt < 8; nt++)
            #pragma unroll
            for (int q = 0; q < 4; q++) acc[mi][nt][q] = 0.0f;

    auto load_chunk = [&](int c, int s) {
        const uint32_t base = sb + s * K2_STAGE;
        const int k0 = c * 64;
        #pragma unroll
        for (int t = 0; t < 2; t++) {
            int ci = tid + t * 512;
            int row = ci >> 3, un = ci & 7;
            uint32_t sa = base + SWA(row * 128 + un * 16);
            cp16(sa, g_WcH + (size_t)row * KTOT + k0 + un * 8);
        }
        #pragma unroll
        for (int t = 0; t < 4; t++) {
            int ci = tid + t * 512;
            int row = ci >> 5, un = ci & 31;
            uint32_t sa = base + 16384 + SWC(row * 512 + un * 16);
            cp16(sa, g_m + (size_t)(k0 + row) * NPIX + n0 + un * 8);
        }
        CP_COMMIT();
    };

    load_chunk(0, 0);
    load_chunk(1, 1);
    load_chunk(2, 2);

    int s = 0;
    for (int c = 0; c < 16; c++) {
        if (c >= 15)      { CP_WAIT0(); }
        else if (c == 14) { CP_WAIT1(); }
        else              { CP_WAIT2(); }
        __syncthreads();

        const uint32_t bA = sb + s * K2_STAGE;
        const uint32_t bB = bA + 16384;

        #pragma unroll
        for (int ks = 0; ks < 4; ks++) {
            uint32_t a_h[2][4];
            {
                int arow  = wm + (lane & 15);
                int acolb = ks * 32 + ((lane >> 4) << 4);
                #pragma unroll
                for (int mi = 0; mi < 2; mi++) {
                    uint32_t off = SWA((arow + mi * 16) * 128 + acolb);
                    ldsm4(a_h[mi], bA + off);
                }
            }
            int browb = (ks * 16 + (lane & 15)) * 512;
            #pragma unroll
            for (int g = 0; g < 4; g++) {
                uint32_t off = SWC(browb + (wn + g * 16 + ((lane >> 4) << 3)) * 2);
                uint32_t bh[4];
                ldsm4t(bh, bB + off);
                #pragma unroll
                for (int mi = 0; mi < 2; mi++) {
                    mma16816(acc[mi][2*g],   a_h[mi], bh);
                    mma16816(acc[mi][2*g+1], a_h[mi], bh + 2);
                }
            }
        }
        __syncthreads();
        if (c + 3 < 16) load_chunk(c + 3, s);
        s = (s == 2) ? 0 : (s + 1);
    }

    const int bz = n0 >> 14;
    const int ncb = n0 & 16383;
    #pragma unroll
    for (int mi = 0; mi < 2; mi++) {
        int r0 = wm + mi * 16 + (lane >> 2);
        float bv0 = bc[r0], bv1 = bc[r0 + 8];
        float* row0 = out + ((size_t)(bz * COUT + r0))     * 16384 + ncb;
        float* row1 = out + ((size_t)(bz * COUT + r0 + 8)) * 16384 + ncb;
        #pragma unroll
        for (int nt = 0; nt < 8; nt++) {
            int col = wn + nt * 8 + (lane & 3) * 2;
            float2 v0, v1;
            v0.x = acc[mi][nt][0] + bv0; v0.y = acc[mi][nt][1] + bv0;
            v1.x = acc[mi][nt][2] + bv1; v1.y = acc[mi][nt][3] + bv1;
            *(float2*)(row0 + col) = v0;
            *(float2*)(row1 + col) = v1;
        }
    }
}

extern "C" void kernel_launch(void* const* d_in, const int* in_sizes, int n_in,
                              void* d_out, int out_size) {
    const float* x  = (const float*)d_in[0];
    const float* r  = (const float*)d_in[1];
    const float* W1 = (const float*)d_in[2];
    const float* b1 = (const float*)d_in[3];
    const float* W2 = (const float*)d_in[4];
    const float* b2 = (const float*)d_in[5];
    const float* Wc = (const float*)d_in[6];
    const float* bc = (const float*)d_in[7];
    float* out = (float*)d_out;

    cudaFuncSetAttribute(k1_weights, cudaFuncAttributeMaxDynamicSharedMemorySize, SM1_BYTES);
    cudaFuncSetAttribute(k2_hmma, cudaFuncAttributeMaxDynamicSharedMemorySize, K2_SMEM);

    float* rcout = (out_size > OUT0) ? (out + OUT0) : nullptr;

    k0_prep<<<(COUT * KTOT + 255) / 256, 256>>>(Wc, W2, W1);
    dim3 g1(32, 32, 4);
    k1_weights<<<g1, 256, SM1_BYTES>>>(x, r, W1, b1, b2, rcout);
    k2_hmma<<<256, 512, K2_SMEM>>>(bc, out);
}